// round 1
// baseline (speedup 1.0000x reference)
#include <cuda_runtime.h>

#define EMBED   1024
#define HEADS   16
#define HDIM    64
#define BATCH   2
#define SEQ     2048
#define MTOT    (BATCH*SEQ)   // 4096

// Scratch (static __device__ -- no dynamic allocation allowed)
__device__ float g_qkv [(size_t)MTOT * 3 * EMBED];   // [4096, 3072]
__device__ float g_attn[(size_t)MTOT * EMBED];       // [4096, 1024]

// ---------------------------------------------------------------------------
// SGEMM (NT): C[M,N] = A[M,K] @ B[N,K]^T + bias[N]
// BM=BN=128, BK=16, 256 threads, 8x8 microtile per thread.
// ---------------------------------------------------------------------------
#define BM 128
#define BN 128
#define BK 16

__global__ __launch_bounds__(256, 2)
void sgemm_nt_bias(const float* __restrict__ A,
                   const float* __restrict__ B,
                   const float* __restrict__ bias,
                   float* __restrict__ C,
                   int M, int N, int K)
{
    __shared__ float As[BK][BM + 4];
    __shared__ float Bs[BK][BN + 4];

    const int tid = threadIdx.x;
    const int tx  = tid & 15;          // n-dim
    const int ty  = tid >> 4;          // m-dim
    const int m0  = blockIdx.y * BM;
    const int n0  = blockIdx.x * BN;

    const int lrow = tid >> 2;         // 0..63
    const int lk   = (tid & 3) * 4;    // 0,4,8,12

    float acc[8][8];
#pragma unroll
    for (int i = 0; i < 8; i++)
#pragma unroll
        for (int j = 0; j < 8; j++) acc[i][j] = 0.f;

    const float* Aptr = A + (size_t)(m0 + lrow) * K + lk;
    const float* Bptr = B + (size_t)(n0 + lrow) * K + lk;

    for (int k0 = 0; k0 < K; k0 += BK) {
        float4 a0 = *(const float4*)(Aptr + k0);
        float4 a1 = *(const float4*)(Aptr + (size_t)64 * K + k0);
        float4 b0 = *(const float4*)(Bptr + k0);
        float4 b1 = *(const float4*)(Bptr + (size_t)64 * K + k0);

        __syncthreads();   // previous stage's compute done before overwrite
        As[lk+0][lrow]      = a0.x; As[lk+1][lrow]      = a0.y;
        As[lk+2][lrow]      = a0.z; As[lk+3][lrow]      = a0.w;
        As[lk+0][lrow+64]   = a1.x; As[lk+1][lrow+64]   = a1.y;
        As[lk+2][lrow+64]   = a1.z; As[lk+3][lrow+64]   = a1.w;
        Bs[lk+0][lrow]      = b0.x; Bs[lk+1][lrow]      = b0.y;
        Bs[lk+2][lrow]      = b0.z; Bs[lk+3][lrow]      = b0.w;
        Bs[lk+0][lrow+64]   = b1.x; Bs[lk+1][lrow+64]   = b1.y;
        Bs[lk+2][lrow+64]   = b1.z; Bs[lk+3][lrow+64]   = b1.w;
        __syncthreads();

#pragma unroll
        for (int kk = 0; kk < BK; kk++) {
            float4 av0 = *(const float4*)&As[kk][ty * 8];
            float4 av1 = *(const float4*)&As[kk][ty * 8 + 4];
            float4 bv0 = *(const float4*)&Bs[kk][tx * 8];
            float4 bv1 = *(const float4*)&Bs[kk][tx * 8 + 4];
            float a[8]  = {av0.x, av0.y, av0.z, av0.w, av1.x, av1.y, av1.z, av1.w};
            float bb[8] = {bv0.x, bv0.y, bv0.z, bv0.w, bv1.x, bv1.y, bv1.z, bv1.w};
#pragma unroll
            for (int i = 0; i < 8; i++)
#pragma unroll
                for (int j = 0; j < 8; j++)
                    acc[i][j] = fmaf(a[i], bb[j], acc[i][j]);
        }
    }

#pragma unroll
    for (int i = 0; i < 8; i++) {
        const int m = m0 + ty * 8 + i;
#pragma unroll
        for (int j4 = 0; j4 < 8; j4 += 4) {
            const int n = n0 + tx * 8 + j4;
            float4 v;
            v.x = acc[i][j4 + 0] + bias[n + 0];
            v.y = acc[i][j4 + 1] + bias[n + 1];
            v.z = acc[i][j4 + 2] + bias[n + 2];
            v.w = acc[i][j4 + 3] + bias[n + 3];
            *(float4*)&C[(size_t)m * N + n] = v;
        }
    }
}

// ---------------------------------------------------------------------------
// Flash attention, fp32. One block = 64 query rows for one (b,h).
// Streams 32-key tiles: S = QK^T/8 (masked) -> online softmax -> O += P V.
// Thread map: ty = tid/16 owns 4 q-rows, tx = tid%16 owns 2 score-cols / 4 d-cols.
// Row reductions via width-16 shfl (a fixed-ty group is a contiguous 16-lane half-warp).
// ---------------------------------------------------------------------------
#define FBM 64
#define FBN 32

__global__ __launch_bounds__(256, 2)
void flash_attn(const float* __restrict__ qkv,
                const int*   __restrict__ mask,
                float*       __restrict__ out)
{
    __shared__ float Qs[FBM * 65];   // [row][d], stride 65 (bank spread)
    __shared__ float Ks[FBN * 65];   // [key][d]
    __shared__ float Vs[FBN * 65];   // [key][d]
    __shared__ float Ps[FBM * 33];   // [row][key]
    __shared__ int   Ms[FBN];

    const int tid = threadIdx.x;
    const int tx  = tid & 15;
    const int ty  = tid >> 4;
    const int qb  = blockIdx.x;   // 0..31
    const int h   = blockIdx.y;   // 0..15
    const int b   = blockIdx.z;   // 0..1

    const size_t rs = 3 * EMBED;  // qkv row stride
    const float* qbase = qkv + (size_t)(b * SEQ) * rs + h * HDIM;
    const float* kbase = qbase + EMBED;
    const float* vbase = qbase + 2 * EMBED;
    const int*   mbase = mask + b * SEQ;

    // Load Q tile [64 x 64]
    for (int e = tid; e < FBM * HDIM; e += 256) {
        const int r = e >> 6, d = e & 63;
        Qs[r * 65 + d] = qbase[(size_t)(qb * FBM + r) * rs + d];
    }

    float m_i[4], l_i[4], o[4][4];
#pragma unroll
    for (int i = 0; i < 4; i++) {
        m_i[i] = -1e30f; l_i[i] = 0.f;
#pragma unroll
        for (int j = 0; j < 4; j++) o[i][j] = 0.f;
    }

    for (int k0 = 0; k0 < SEQ; k0 += FBN) {
        __syncthreads();   // prior PV reads of Ks/Vs complete
        for (int e = tid; e < FBN * HDIM; e += 256) {
            const int r = e >> 6, d = e & 63;
            Ks[r * 65 + d] = kbase[(size_t)(k0 + r) * rs + d];
            Vs[r * 65 + d] = vbase[(size_t)(k0 + r) * rs + d];
        }
        if (tid < FBN) Ms[tid] = mbase[k0 + tid];
        __syncthreads();

        // ---- scores: s[i][j] = q_row(ty*4+i) . k_col(tx*2+j) ----
        float s[4][2];
#pragma unroll
        for (int i = 0; i < 4; i++) { s[i][0] = 0.f; s[i][1] = 0.f; }
#pragma unroll 8
        for (int kk = 0; kk < HDIM; kk++) {
            float q0 = Qs[(ty * 4 + 0) * 65 + kk];
            float q1 = Qs[(ty * 4 + 1) * 65 + kk];
            float q2 = Qs[(ty * 4 + 2) * 65 + kk];
            float q3 = Qs[(ty * 4 + 3) * 65 + kk];
            float f0 = Ks[(tx * 2 + 0) * 65 + kk];
            float f1 = Ks[(tx * 2 + 1) * 65 + kk];
            s[0][0] = fmaf(q0, f0, s[0][0]); s[0][1] = fmaf(q0, f1, s[0][1]);
            s[1][0] = fmaf(q1, f0, s[1][0]); s[1][1] = fmaf(q1, f1, s[1][1]);
            s[2][0] = fmaf(q2, f0, s[2][0]); s[2][1] = fmaf(q2, f1, s[2][1]);
            s[3][0] = fmaf(q3, f0, s[3][0]); s[3][1] = fmaf(q3, f1, s[3][1]);
        }
        const int mk0 = Ms[tx * 2 + 0];
        const int mk1 = Ms[tx * 2 + 1];
#pragma unroll
        for (int i = 0; i < 4; i++) {
            s[i][0] = (mk0 == 0) ? -1e30f : s[i][0] * 0.125f;
            s[i][1] = (mk1 == 0) ? -1e30f : s[i][1] * 0.125f;
        }

        // ---- online softmax update ----
        float p[4][2], corr[4];
#pragma unroll
        for (int i = 0; i < 4; i++) {
            float rmax = fmaxf(s[i][0], s[i][1]);
            rmax = fmaxf(rmax, __shfl_xor_sync(0xffffffffu, rmax, 1, 16));
            rmax = fmaxf(rmax, __shfl_xor_sync(0xffffffffu, rmax, 2, 16));
            rmax = fmaxf(rmax, __shfl_xor_sync(0xffffffffu, rmax, 4, 16));
            rmax = fmaxf(rmax, __shfl_xor_sync(0xffffffffu, rmax, 8, 16));
            const float mnew = fmaxf(m_i[i], rmax);
            corr[i] = __expf(m_i[i] - mnew);
            p[i][0] = __expf(s[i][0] - mnew);
            p[i][1] = __expf(s[i][1] - mnew);
            float rsum = p[i][0] + p[i][1];
            rsum += __shfl_xor_sync(0xffffffffu, rsum, 1, 16);
            rsum += __shfl_xor_sync(0xffffffffu, rsum, 2, 16);
            rsum += __shfl_xor_sync(0xffffffffu, rsum, 4, 16);
            rsum += __shfl_xor_sync(0xffffffffu, rsum, 8, 16);
            l_i[i] = l_i[i] * corr[i] + rsum;
            m_i[i] = mnew;
#pragma unroll
            for (int j = 0; j < 4; j++) o[i][j] *= corr[i];
            Ps[(ty * 4 + i) * 33 + tx * 2 + 0] = p[i][0];
            Ps[(ty * 4 + i) * 33 + tx * 2 + 1] = p[i][1];
        }
        __syncthreads();

        // ---- O += P @ V  (d-cols = tx*4+j) ----
#pragma unroll 8
        for (int kk = 0; kk < FBN; kk++) {
            float pf0 = Ps[(ty * 4 + 0) * 33 + kk];
            float pf1 = Ps[(ty * 4 + 1) * 33 + kk];
            float pf2 = Ps[(ty * 4 + 2) * 33 + kk];
            float pf3 = Ps[(ty * 4 + 3) * 33 + kk];
            float v0  = Vs[kk * 65 + tx * 4 + 0];
            float v1  = Vs[kk * 65 + tx * 4 + 1];
            float v2  = Vs[kk * 65 + tx * 4 + 2];
            float v3  = Vs[kk * 65 + tx * 4 + 3];
            o[0][0] = fmaf(pf0, v0, o[0][0]); o[0][1] = fmaf(pf0, v1, o[0][1]);
            o[0][2] = fmaf(pf0, v2, o[0][2]); o[0][3] = fmaf(pf0, v3, o[0][3]);
            o[1][0] = fmaf(pf1, v0, o[1][0]); o[1][1] = fmaf(pf1, v1, o[1][1]);
            o[1][2] = fmaf(pf1, v2, o[1][2]); o[1][3] = fmaf(pf1, v3, o[1][3]);
            o[2][0] = fmaf(pf2, v0, o[2][0]); o[2][1] = fmaf(pf2, v1, o[2][1]);
            o[2][2] = fmaf(pf2, v2, o[2][2]); o[2][3] = fmaf(pf2, v3, o[2][3]);
            o[3][0] = fmaf(pf3, v0, o[3][0]); o[3][1] = fmaf(pf3, v1, o[3][1]);
            o[3][2] = fmaf(pf3, v2, o[3][2]); o[3][3] = fmaf(pf3, v3, o[3][3]);
        }
    }

    // epilogue: normalize and store to [b, s, h*64+d] layout (contiguous for GEMM2)
#pragma unroll
    for (int i = 0; i < 4; i++) {
        const float inv = 1.0f / l_i[i];
        const int s_glob = qb * FBM + ty * 4 + i;
        float* dst = out + (size_t)(b * SEQ + s_glob) * EMBED + h * HDIM + tx * 4;
        float4 v;
        v.x = o[i][0] * inv; v.y = o[i][1] * inv;
        v.z = o[i][2] * inv; v.w = o[i][3] * inv;
        *(float4*)dst = v;
    }
}

// ---------------------------------------------------------------------------
extern "C" void kernel_launch(void* const* d_in, const int* in_sizes, int n_in,
                              void* d_out, int out_size)
{
    const float* x    = (const float*)d_in[0];
    const int*   mask = (const int*)  d_in[1];
    const float* Wqkv = (const float*)d_in[2];
    const float* bqkv = (const float*)d_in[3];
    const float* Wout = (const float*)d_in[4];
    const float* bout = (const float*)d_in[5];
    float* out = (float*)d_out;

    float *qkv = nullptr, *attn = nullptr;
    cudaGetSymbolAddress((void**)&qkv,  g_qkv);
    cudaGetSymbolAddress((void**)&attn, g_attn);

    // 1) qkv = x @ Wqkv^T + bqkv       [4096, 3072]
    {
        dim3 grid((3 * EMBED) / BN, MTOT / BM);
        sgemm_nt_bias<<<grid, 256>>>(x, Wqkv, bqkv, qkv, MTOT, 3 * EMBED, EMBED);
    }
    // 2) flash attention -> attn       [4096, 1024] (already b,s,e layout)
    {
        dim3 grid(SEQ / FBM, HEADS, BATCH);
        flash_attn<<<grid, 256>>>(qkv, mask, attn);
    }
    // 3) out = attn @ Wout^T + bout    [4096, 1024]
    {
        dim3 grid(EMBED / BN, MTOT / BM);
        sgemm_nt_bias<<<grid, 256>>>(attn, Wout, bout, out, MTOT, EMBED, EMBED);
    }
}

// round 3
// speedup vs baseline: 1.2838x; 1.2838x over previous
#include <cuda_runtime.h>
#include <cstdint>

#define EMBED   1024
#define HEADS   16
#define HDIM    64
#define BATCH   2
#define SEQ     2048
#define MTOT    (BATCH*SEQ)   // 4096

// Scratch (static __device__ -- no dynamic allocation allowed)
__device__ float g_qkv [(size_t)MTOT * 3 * EMBED];   // [4096, 3072]
__device__ float g_attn[(size_t)MTOT * EMBED];       // [4096, 1024]

// ============================================================================
// helpers
// ============================================================================
__device__ __forceinline__ uint32_t smem_u32(const void* p) {
    uint32_t a;
    asm("{ .reg .u64 t; cvta.to.shared.u64 t, %1; cvt.u32.u64 %0, t; }"
        : "=r"(a) : "l"(p));
    return a;
}
// fp32 -> tf32, round-to-nearest (unbiased)
__device__ __forceinline__ float f2tf32(float x) {
    uint32_t u;
    asm("cvt.rna.tf32.f32 %0, %1;" : "=r"(u) : "f"(x));
    return __uint_as_float(u);
}
__device__ __forceinline__ void ldsm_x4(uint32_t* r, uint32_t addr) {
    asm volatile("ldmatrix.sync.aligned.m8n8.x4.shared.b16 {%0,%1,%2,%3}, [%4];"
        : "=r"(r[0]), "=r"(r[1]), "=r"(r[2]), "=r"(r[3]) : "r"(addr));
}
__device__ __forceinline__ void ldsm_x2(uint32_t* r, uint32_t addr) {
    asm volatile("ldmatrix.sync.aligned.m8n8.x2.shared.b16 {%0,%1}, [%2];"
        : "=r"(r[0]), "=r"(r[1]) : "r"(addr));
}
__device__ __forceinline__ void mma_tf32(float* d, const uint32_t* a, const uint32_t* b) {
    asm volatile(
        "mma.sync.aligned.m16n8k8.row.col.f32.tf32.tf32.f32 "
        "{%0,%1,%2,%3}, {%4,%5,%6,%7}, {%8,%9}, {%0,%1,%2,%3};"
        : "+f"(d[0]), "+f"(d[1]), "+f"(d[2]), "+f"(d[3])
        : "r"(a[0]), "r"(a[1]), "r"(a[2]), "r"(a[3]), "r"(b[0]), "r"(b[1]));
}

// ============================================================================
// tf32 tensor-core GEMM (NT): C[M,N] = A[M,K] @ B[N,K]^T + bias[N]
// CTA 128x128, BK=32 floats (128B rows, XOR-swizzled), 256 thr = 8 warps in
// 2(m) x 4(n); warp tile 64x32 -> 4x4 m16n8k8 mma per K8 step, 4 steps/iter.
// Single smem stage (32 KB static), register prefetch of the next tile.
// ============================================================================
#define BKF 32   // K floats per mainloop iter

__global__ __launch_bounds__(256, 1)
void gemm_tf32_mma(const float* __restrict__ A,
                   const float* __restrict__ B,
                   const float* __restrict__ bias,
                   float* __restrict__ C,
                   int M, int N, int K)
{
    __shared__ float sA[128 * BKF];   // [m][k] 128B rows, swizzled
    __shared__ float sB[128 * BKF];   // [n][k]

    const int tid  = threadIdx.x;
    const int wid  = tid >> 5;
    const int lane = tid & 31;
    const int m0   = blockIdx.y * 128;
    const int n0   = blockIdx.x * 128;
    const int wm   = (wid & 1) * 64;   // warp m offset in tile
    const int wn   = (wid >> 1) * 32;  // warp n offset in tile

    const uint32_t sAa = smem_u32(sA);
    const uint32_t sBa = smem_u32(sB);

    // ---- loader mapping: row = tid>>1 (0..127), half = tid&1 -> 16 floats
    const int lrow  = tid >> 1;
    const int lhalf = tid & 1;
    const float* Arow = A + (size_t)(m0 + lrow) * K + lhalf * 16;
    const float* Brow = B + (size_t)(n0 + lrow) * K + lhalf * 16;
    // swizzled byte offsets for the 4 float4 stores (constant per thread)
    uint32_t st_off[4];
#pragma unroll
    for (int q = 0; q < 4; q++) {
        uint32_t bo = (uint32_t)lrow * 128u + (uint32_t)lhalf * 64u + q * 16u;
        st_off[q] = bo ^ ((bo >> 3) & 0x70);
    }

    // ---- ldmatrix per-thread address patterns (row part + swizzle mask)
    // A x4: seg = lane>>3: row += (seg&1)*8, kb = (seg>>1)*16
    const int aseg  = lane >> 3;
    const int arow  = wm + ((aseg & 1) << 3) + (lane & 7);   // within 0..127 (m)
    const uint32_t akb = (uint32_t)((aseg >> 1) << 4);
    // B x2: lanes 0-7 -> kb 0, lanes 8-15 -> kb 16 (lanes 16-31 replicate)
    const int bseg  = (lane >> 3) & 1;
    const int brow  = wn + (lane & 7);                       // within 0..127 (n)
    const uint32_t bkb = (uint32_t)(bseg << 4);
    const uint32_t swmask = (uint32_t)((lane & 7) << 4);     // XOR of k-col bits

    const uint32_t aRowByte = (uint32_t)arow * 128u;
    const uint32_t bRowByte = (uint32_t)brow * 128u;

    float acc[4][4][4];
#pragma unroll
    for (int i = 0; i < 4; i++)
#pragma unroll
        for (int j = 0; j < 4; j++)
#pragma unroll
            for (int r = 0; r < 4; r++) acc[i][j][r] = 0.f;

    const int KCH = K / BKF;
    float4 av[4], bv[4];
    // preload iter 0
#pragma unroll
    for (int q = 0; q < 4; q++) {
        av[q] = *(const float4*)(Arow + q * 4);
        bv[q] = *(const float4*)(Brow + q * 4);
    }

    for (int kt = 0; kt < KCH; kt++) {
        // store prefetched tile (convert to tf32)
#pragma unroll
        for (int q = 0; q < 4; q++) {
            float4 t;
            t.x = f2tf32(av[q].x); t.y = f2tf32(av[q].y);
            t.z = f2tf32(av[q].z); t.w = f2tf32(av[q].w);
            *(float4*)((char*)sA + st_off[q]) = t;
            t.x = f2tf32(bv[q].x); t.y = f2tf32(bv[q].y);
            t.z = f2tf32(bv[q].z); t.w = f2tf32(bv[q].w);
            *(float4*)((char*)sB + st_off[q]) = t;
        }
        __syncthreads();

        // prefetch next tile
        if (kt + 1 < KCH) {
            const float* a = Arow + (size_t)(kt + 1) * BKF;
            const float* b = Brow + (size_t)(kt + 1) * BKF;
#pragma unroll
            for (int q = 0; q < 4; q++) {
                av[q] = *(const float4*)(a + q * 4);
                bv[q] = *(const float4*)(b + q * 4);
            }
        }

        // compute: 4 K8 steps
#pragma unroll
        for (int ks = 0; ks < 4; ks++) {
            const uint32_t kcolA = ((uint32_t)(ks * 32) + akb) ^ swmask;
            const uint32_t kcolB = ((uint32_t)(ks * 32) + bkb) ^ swmask;
            uint32_t afr[4][4], bfr[4][2];
#pragma unroll
            for (int mt = 0; mt < 4; mt++)
                ldsm_x4(afr[mt], sAa + aRowByte + (uint32_t)(mt * 16 * 128) + kcolA);
#pragma unroll
            for (int nt = 0; nt < 4; nt++)
                ldsm_x2(bfr[nt], sBa + bRowByte + (uint32_t)(nt * 8 * 128) + kcolB);
#pragma unroll
            for (int mt = 0; mt < 4; mt++)
#pragma unroll
                for (int nt = 0; nt < 4; nt++)
                    mma_tf32(acc[mt][nt], afr[mt], bfr[nt]);
        }
        __syncthreads();
    }

    // ---- epilogue: direct global stores (float2 pairs) + bias
    const int rbase = m0 + wm + (lane >> 2);
    const int cbase = n0 + wn + (lane & 3) * 2;
#pragma unroll
    for (int mt = 0; mt < 4; mt++) {
        const int r0 = rbase + mt * 16;
#pragma unroll
        for (int nt = 0; nt < 4; nt++) {
            const int c = cbase + nt * 8;
            const float b0 = __ldg(bias + c);
            const float b1 = __ldg(bias + c + 1);
            float2 v0, v1;
            v0.x = acc[mt][nt][0] + b0; v0.y = acc[mt][nt][1] + b1;
            v1.x = acc[mt][nt][2] + b0; v1.y = acc[mt][nt][3] + b1;
            *(float2*)&C[(size_t)r0 * N + c]       = v0;
            *(float2*)&C[(size_t)(r0 + 8) * N + c] = v1;
        }
    }
}

// ---------------------------------------------------------------------------
// Flash attention, fp32 (unchanged — tensor-core port is the next target).
// ---------------------------------------------------------------------------
#define FBM 64
#define FBN 32

__global__ __launch_bounds__(256, 2)
void flash_attn(const float* __restrict__ qkv,
                const int*   __restrict__ mask,
                float*       __restrict__ out)
{
    __shared__ float Qs[FBM * 65];
    __shared__ float Ks[FBN * 65];
    __shared__ float Vs[FBN * 65];
    __shared__ float Ps[FBM * 33];
    __shared__ int   Ms[FBN];

    const int tid = threadIdx.x;
    const int tx  = tid & 15;
    const int ty  = tid >> 4;
    const int qb  = blockIdx.x;
    const int h   = blockIdx.y;
    const int b   = blockIdx.z;

    const size_t rs = 3 * EMBED;
    const float* qbase = qkv + (size_t)(b * SEQ) * rs + h * HDIM;
    const float* kbase = qbase + EMBED;
    const float* vbase = qbase + 2 * EMBED;
    const int*   mbase = mask + b * SEQ;

    for (int e = tid; e < FBM * HDIM; e += 256) {
        const int r = e >> 6, d = e & 63;
        Qs[r * 65 + d] = qbase[(size_t)(qb * FBM + r) * rs + d];
    }

    float m_i[4], l_i[4], o[4][4];
#pragma unroll
    for (int i = 0; i < 4; i++) {
        m_i[i] = -1e30f; l_i[i] = 0.f;
#pragma unroll
        for (int j = 0; j < 4; j++) o[i][j] = 0.f;
    }

    for (int k0 = 0; k0 < SEQ; k0 += FBN) {
        __syncthreads();
        for (int e = tid; e < FBN * HDIM; e += 256) {
            const int r = e >> 6, d = e & 63;
            Ks[r * 65 + d] = kbase[(size_t)(k0 + r) * rs + d];
            Vs[r * 65 + d] = vbase[(size_t)(k0 + r) * rs + d];
        }
        if (tid < FBN) Ms[tid] = mbase[k0 + tid];
        __syncthreads();

        float s[4][2];
#pragma unroll
        for (int i = 0; i < 4; i++) { s[i][0] = 0.f; s[i][1] = 0.f; }
#pragma unroll 8
        for (int kk = 0; kk < HDIM; kk++) {
            float q0 = Qs[(ty * 4 + 0) * 65 + kk];
            float q1 = Qs[(ty * 4 + 1) * 65 + kk];
            float q2 = Qs[(ty * 4 + 2) * 65 + kk];
            float q3 = Qs[(ty * 4 + 3) * 65 + kk];
            float f0 = Ks[(tx * 2 + 0) * 65 + kk];
            float f1 = Ks[(tx * 2 + 1) * 65 + kk];
            s[0][0] = fmaf(q0, f0, s[0][0]); s[0][1] = fmaf(q0, f1, s[0][1]);
            s[1][0] = fmaf(q1, f0, s[1][0]); s[1][1] = fmaf(q1, f1, s[1][1]);
            s[2][0] = fmaf(q2, f0, s[2][0]); s[2][1] = fmaf(q2, f1, s[2][1]);
            s[3][0] = fmaf(q3, f0, s[3][0]); s[3][1] = fmaf(q3, f1, s[3][1]);
        }
        const int mk0 = Ms[tx * 2 + 0];
        const int mk1 = Ms[tx * 2 + 1];
#pragma unroll
        for (int i = 0; i < 4; i++) {
            s[i][0] = (mk0 == 0) ? -1e30f : s[i][0] * 0.125f;
            s[i][1] = (mk1 == 0) ? -1e30f : s[i][1] * 0.125f;
        }

        float p[4][2], corr[4];
#pragma unroll
        for (int i = 0; i < 4; i++) {
            float rmax = fmaxf(s[i][0], s[i][1]);
            rmax = fmaxf(rmax, __shfl_xor_sync(0xffffffffu, rmax, 1, 16));
            rmax = fmaxf(rmax, __shfl_xor_sync(0xffffffffu, rmax, 2, 16));
            rmax = fmaxf(rmax, __shfl_xor_sync(0xffffffffu, rmax, 4, 16));
            rmax = fmaxf(rmax, __shfl_xor_sync(0xffffffffu, rmax, 8, 16));
            const float mnew = fmaxf(m_i[i], rmax);
            corr[i] = __expf(m_i[i] - mnew);
            p[i][0] = __expf(s[i][0] - mnew);
            p[i][1] = __expf(s[i][1] - mnew);
            float rsum = p[i][0] + p[i][1];
            rsum += __shfl_xor_sync(0xffffffffu, rsum, 1, 16);
            rsum += __shfl_xor_sync(0xffffffffu, rsum, 2, 16);
            rsum += __shfl_xor_sync(0xffffffffu, rsum, 4, 16);
            rsum += __shfl_xor_sync(0xffffffffu, rsum, 8, 16);
            l_i[i] = l_i[i] * corr[i] + rsum;
            m_i[i] = mnew;
#pragma unroll
            for (int j = 0; j < 4; j++) o[i][j] *= corr[i];
            Ps[(ty * 4 + i) * 33 + tx * 2 + 0] = p[i][0];
            Ps[(ty * 4 + i) * 33 + tx * 2 + 1] = p[i][1];
        }
        __syncthreads();

#pragma unroll 8
        for (int kk = 0; kk < FBN; kk++) {
            float pf0 = Ps[(ty * 4 + 0) * 33 + kk];
            float pf1 = Ps[(ty * 4 + 1) * 33 + kk];
            float pf2 = Ps[(ty * 4 + 2) * 33 + kk];
            float pf3 = Ps[(ty * 4 + 3) * 33 + kk];
            float v0  = Vs[kk * 65 + tx * 4 + 0];
            float v1  = Vs[kk * 65 + tx * 4 + 1];
            float v2  = Vs[kk * 65 + tx * 4 + 2];
            float v3  = Vs[kk * 65 + tx * 4 + 3];
            o[0][0] = fmaf(pf0, v0, o[0][0]); o[0][1] = fmaf(pf0, v1, o[0][1]);
            o[0][2] = fmaf(pf0, v2, o[0][2]); o[0][3] = fmaf(pf0, v3, o[0][3]);
            o[1][0] = fmaf(pf1, v0, o[1][0]); o[1][1] = fmaf(pf1, v1, o[1][1]);
            o[1][2] = fmaf(pf1, v2, o[1][2]); o[1][3] = fmaf(pf1, v3, o[1][3]);
            o[2][0] = fmaf(pf2, v0, o[2][0]); o[2][1] = fmaf(pf2, v1, o[2][1]);
            o[2][2] = fmaf(pf2, v2, o[2][2]); o[2][3] = fmaf(pf2, v3, o[2][3]);
            o[3][0] = fmaf(pf3, v0, o[3][0]); o[3][1] = fmaf(pf3, v1, o[3][1]);
            o[3][2] = fmaf(pf3, v2, o[3][2]); o[3][3] = fmaf(pf3, v3, o[3][3]);
        }
    }

#pragma unroll
    for (int i = 0; i < 4; i++) {
        const float inv = 1.0f / l_i[i];
        const int s_glob = qb * FBM + ty * 4 + i;
        float* dst = out + (size_t)(b * SEQ + s_glob) * EMBED + h * HDIM + tx * 4;
        float4 v;
        v.x = o[i][0] * inv; v.y = o[i][1] * inv;
        v.z = o[i][2] * inv; v.w = o[i][3] * inv;
        *(float4*)dst = v;
    }
}

// ---------------------------------------------------------------------------
extern "C" void kernel_launch(void* const* d_in, const int* in_sizes, int n_in,
                              void* d_out, int out_size)
{
    const float* x    = (const float*)d_in[0];
    const int*   mask = (const int*)  d_in[1];
    const float* Wqkv = (const float*)d_in[2];
    const float* bqkv = (const float*)d_in[3];
    const float* Wout = (const float*)d_in[4];
    const float* bout = (const float*)d_in[5];
    float* out = (float*)d_out;

    float *qkv = nullptr, *attn = nullptr;
    cudaGetSymbolAddress((void**)&qkv,  g_qkv);
    cudaGetSymbolAddress((void**)&attn, g_attn);

    // 1) qkv = x @ Wqkv^T + bqkv       [4096, 3072]  (tf32 mma.sync)
    {
        dim3 grid((3 * EMBED) / 128, MTOT / 128);
        gemm_tf32_mma<<<grid, 256>>>(x, Wqkv, bqkv, qkv, MTOT, 3 * EMBED, EMBED);
    }
    // 2) flash attention -> attn       [4096, 1024]
    {
        dim3 grid(SEQ / FBM, HEADS, BATCH);
        flash_attn<<<grid, 256>>>(qkv, mask, attn);
    }
    // 3) out = attn @ Wout^T + bout    [4096, 1024]  (tf32 mma.sync)
    {
        dim3 grid(EMBED / 128, MTOT / 128);
        gemm_tf32_mma<<<grid, 256>>>(attn, Wout, bout, out, MTOT, EMBED, EMBED);
    }
}

// round 4
// speedup vs baseline: 2.6065x; 2.0303x over previous
#include <cuda_runtime.h>
#include <cstdint>

#define EMBED   1024
#define HEADS   16
#define HDIM    64
#define BATCH   2
#define SEQ     2048
#define MTOT    (BATCH*SEQ)   // 4096

// Scratch (static __device__ -- no dynamic allocation allowed)
__device__ float g_qkv [(size_t)MTOT * 3 * EMBED];   // [4096, 3072]
__device__ float g_attn[(size_t)MTOT * EMBED];       // [4096, 1024]

// ============================================================================
// helpers
// ============================================================================
__device__ __forceinline__ uint32_t smem_u32(const void* p) {
    uint32_t a;
    asm("{ .reg .u64 t; cvta.to.shared.u64 t, %1; cvt.u32.u64 %0, t; }"
        : "=r"(a) : "l"(p));
    return a;
}
// fp32 -> tf32, round-to-nearest (unbiased)
__device__ __forceinline__ float f2tf32(float x) {
    uint32_t u;
    asm("cvt.rna.tf32.f32 %0, %1;" : "=r"(u) : "f"(x));
    return __uint_as_float(u);
}
__device__ __forceinline__ void ldsm_x4(uint32_t* r, uint32_t addr) {
    asm volatile("ldmatrix.sync.aligned.m8n8.x4.shared.b16 {%0,%1,%2,%3}, [%4];"
        : "=r"(r[0]), "=r"(r[1]), "=r"(r[2]), "=r"(r[3]) : "r"(addr));
}
__device__ __forceinline__ void ldsm_x2(uint32_t* r, uint32_t addr) {
    asm volatile("ldmatrix.sync.aligned.m8n8.x2.shared.b16 {%0,%1}, [%2];"
        : "=r"(r[0]), "=r"(r[1]) : "r"(addr));
}
__device__ __forceinline__ void mma_tf32(float* d, const uint32_t* a, const uint32_t* b) {
    asm volatile(
        "mma.sync.aligned.m16n8k8.row.col.f32.tf32.tf32.f32 "
        "{%0,%1,%2,%3}, {%4,%5,%6,%7}, {%8,%9}, {%0,%1,%2,%3};"
        : "+f"(d[0]), "+f"(d[1]), "+f"(d[2]), "+f"(d[3])
        : "r"(a[0]), "r"(a[1]), "r"(a[2]), "r"(a[3]), "r"(b[0]), "r"(b[1]));
}

// ============================================================================
// tf32 tensor-core GEMM (NT): C[M,N] = A[M,K] @ B[N,K]^T + bias[N]
// (unchanged from round 3 — verified at 270us / 96 TF/s)
// ============================================================================
#define BKF 32   // K floats per mainloop iter

__global__ __launch_bounds__(256, 1)
void gemm_tf32_mma(const float* __restrict__ A,
                   const float* __restrict__ B,
                   const float* __restrict__ bias,
                   float* __restrict__ C,
                   int M, int N, int K)
{
    __shared__ float sA[128 * BKF];
    __shared__ float sB[128 * BKF];

    const int tid  = threadIdx.x;
    const int wid  = tid >> 5;
    const int lane = tid & 31;
    const int m0   = blockIdx.y * 128;
    const int n0   = blockIdx.x * 128;
    const int wm   = (wid & 1) * 64;
    const int wn   = (wid >> 1) * 32;

    const uint32_t sAa = smem_u32(sA);
    const uint32_t sBa = smem_u32(sB);

    const int lrow  = tid >> 1;
    const int lhalf = tid & 1;
    const float* Arow = A + (size_t)(m0 + lrow) * K + lhalf * 16;
    const float* Brow = B + (size_t)(n0 + lrow) * K + lhalf * 16;
    uint32_t st_off[4];
#pragma unroll
    for (int q = 0; q < 4; q++) {
        uint32_t bo = (uint32_t)lrow * 128u + (uint32_t)lhalf * 64u + q * 16u;
        st_off[q] = bo ^ ((bo >> 3) & 0x70);
    }

    const int aseg  = lane >> 3;
    const int arow  = wm + ((aseg & 1) << 3) + (lane & 7);
    const uint32_t akb = (uint32_t)((aseg >> 1) << 4);
    const int bseg  = (lane >> 3) & 1;
    const int brow  = wn + (lane & 7);
    const uint32_t bkb = (uint32_t)(bseg << 4);
    const uint32_t swmask = (uint32_t)((lane & 7) << 4);

    const uint32_t aRowByte = (uint32_t)arow * 128u;
    const uint32_t bRowByte = (uint32_t)brow * 128u;

    float acc[4][4][4];
#pragma unroll
    for (int i = 0; i < 4; i++)
#pragma unroll
        for (int j = 0; j < 4; j++)
#pragma unroll
            for (int r = 0; r < 4; r++) acc[i][j][r] = 0.f;

    const int KCH = K / BKF;
    float4 av[4], bv[4];
#pragma unroll
    for (int q = 0; q < 4; q++) {
        av[q] = *(const float4*)(Arow + q * 4);
        bv[q] = *(const float4*)(Brow + q * 4);
    }

    for (int kt = 0; kt < KCH; kt++) {
#pragma unroll
        for (int q = 0; q < 4; q++) {
            float4 t;
            t.x = f2tf32(av[q].x); t.y = f2tf32(av[q].y);
            t.z = f2tf32(av[q].z); t.w = f2tf32(av[q].w);
            *(float4*)((char*)sA + st_off[q]) = t;
            t.x = f2tf32(bv[q].x); t.y = f2tf32(bv[q].y);
            t.z = f2tf32(bv[q].z); t.w = f2tf32(bv[q].w);
            *(float4*)((char*)sB + st_off[q]) = t;
        }
        __syncthreads();

        if (kt + 1 < KCH) {
            const float* a = Arow + (size_t)(kt + 1) * BKF;
            const float* b = Brow + (size_t)(kt + 1) * BKF;
#pragma unroll
            for (int q = 0; q < 4; q++) {
                av[q] = *(const float4*)(a + q * 4);
                bv[q] = *(const float4*)(b + q * 4);
            }
        }

#pragma unroll
        for (int ks = 0; ks < 4; ks++) {
            const uint32_t kcolA = ((uint32_t)(ks * 32) + akb) ^ swmask;
            const uint32_t kcolB = ((uint32_t)(ks * 32) + bkb) ^ swmask;
            uint32_t afr[4][4], bfr[4][2];
#pragma unroll
            for (int mt = 0; mt < 4; mt++)
                ldsm_x4(afr[mt], sAa + aRowByte + (uint32_t)(mt * 16 * 128) + kcolA);
#pragma unroll
            for (int nt = 0; nt < 4; nt++)
                ldsm_x2(bfr[nt], sBa + bRowByte + (uint32_t)(nt * 8 * 128) + kcolB);
#pragma unroll
            for (int mt = 0; mt < 4; mt++)
#pragma unroll
                for (int nt = 0; nt < 4; nt++)
                    mma_tf32(acc[mt][nt], afr[mt], bfr[nt]);
        }
        __syncthreads();
    }

    const int rbase = m0 + wm + (lane >> 2);
    const int cbase = n0 + wn + (lane & 3) * 2;
#pragma unroll
    for (int mt = 0; mt < 4; mt++) {
        const int r0 = rbase + mt * 16;
#pragma unroll
        for (int nt = 0; nt < 4; nt++) {
            const int c = cbase + nt * 8;
            const float b0 = __ldg(bias + c);
            const float b1 = __ldg(bias + c + 1);
            float2 v0, v1;
            v0.x = acc[mt][nt][0] + b0; v0.y = acc[mt][nt][1] + b1;
            v1.x = acc[mt][nt][2] + b0; v1.y = acc[mt][nt][3] + b1;
            *(float2*)&C[(size_t)r0 * N + c]       = v0;
            *(float2*)&C[(size_t)(r0 + 8) * N + c] = v1;
        }
    }
}

// ============================================================================
// Tensor-core flash attention (tf32 mma).
// CTA: 128 q-rows of one (b,h). 8 warps, 16 q-rows/warp. Key tile 64.
// Smem rows are 64 floats (256B); swizzle: 16B chunk c at row r -> c ^ (r&7).
// S = Q K^T (mma) -> fragment softmax -> P (tf32) -> O += P V^T (mma).
// ============================================================================
#define BQ  128
#define BKV 64

// dynamic smem layout (bytes from 1024-aligned base):
//  sQ  [128][64]f : 0      .. 32768
//  sK  [ 64][64]f : 32768  .. 49152
//  sVT [ 64][64]f : 49152  .. 65536   (indexed [d][key])
//  sP  [128][64]f : 65536  .. 98304
//  sM  [64]i      : 98304  .. 98560
#define FA_SMEM (98560 + 1024)

__device__ __forceinline__ uint32_t sw256(int row, int chunk) {
    // byte offset of 16B chunk `chunk` in 256B row `row`, XOR-swizzled
    return (uint32_t)row * 256u + (uint32_t)((chunk ^ (row & 7)) << 4);
}

__global__ __launch_bounds__(256, 1)
void flash_attn_tc(const float* __restrict__ qkv,
                   const int*   __restrict__ mask,
                   float*       __restrict__ out)
{
    extern __shared__ char fsm[];
    const uint32_t raw  = smem_u32(fsm);
    const uint32_t base = (raw + 1023u) & ~1023u;
    char* pb = fsm + (base - raw);
    char* sQ  = pb;
    char* sK  = pb + 32768;
    char* sVT = pb + 49152;
    char* sP  = pb + 65536;
    int*  sM  = (int*)(pb + 98304);
    const uint32_t aQ  = base;
    const uint32_t aK  = base + 32768;
    const uint32_t aVT = base + 49152;
    const uint32_t aP  = base + 65536;

    const int tid  = threadIdx.x;
    const int wid  = tid >> 5;
    const int lane = tid & 31;
    const int qb   = blockIdx.x;
    const int h    = blockIdx.y;
    const int b    = blockIdx.z;

    const size_t rs = 3 * EMBED;
    const float* qg = qkv + (size_t)(b * SEQ) * rs + h * HDIM;
    const float* kg = qg + EMBED;
    const float* vg = qg + 2 * EMBED;
    const int*   mg = mask + b * SEQ;

    // ---- load Q tile [128][64], tf32-rounded, swizzled
    {
        const int r  = tid >> 1;
        const int cb = (tid & 1) * 8;
        const float* src = qg + (size_t)(qb * BQ + r) * rs;
#pragma unroll
        for (int q = 0; q < 8; q++) {
            const int c = cb + q;
            float4 v = *(const float4*)(src + c * 4);
            v.x = f2tf32(v.x); v.y = f2tf32(v.y);
            v.z = f2tf32(v.z); v.w = f2tf32(v.w);
            *(float4*)(sQ + sw256(r, c)) = v;
        }
    }
    __syncthreads();

    // ---- hoist Q fragments for all 8 k-steps (persistent across k-tiles)
    const int arow = wid * 16 + ((lane >> 3) & 1) * 8 + (lane & 7);  // A-frag row
    const int ach  = lane >> 4;                                      // chunk lo bit
    uint32_t qf[8][4];
#pragma unroll
    for (int ks = 0; ks < 8; ks++)
        ldsm_x4(qf[ks], aQ + sw256(arow, ks * 2 + ach));

    // B-frag addressing pieces
    const int bln = lane & 7;            // row-in-8
    const int bch = (lane >> 3) & 1;     // chunk lo bit

    float m_i[2] = {-1e30f, -1e30f};
    float l_i[2] = {0.f, 0.f};
    float oacc[8][4];
#pragma unroll
    for (int j = 0; j < 8; j++)
#pragma unroll
        for (int r = 0; r < 4; r++) oacc[j][r] = 0.f;

    for (int kt = 0; kt < SEQ / BKV; kt++) {
        __syncthreads();   // prev PV mma done reading sK/sVT/sP

        // ---- load K tile [64 keys][64 d]
        {
            const int r  = tid >> 2;
            const int cb = (tid & 3) * 4;
            const float* src = kg + (size_t)(kt * BKV + r) * rs;
#pragma unroll
            for (int q = 0; q < 4; q++) {
                const int c = cb + q;
                float4 v = *(const float4*)(src + c * 4);
                v.x = f2tf32(v.x); v.y = f2tf32(v.y);
                v.z = f2tf32(v.z); v.w = f2tf32(v.w);
                *(float4*)(sK + sw256(r, c)) = v;
            }
        }
        // ---- load V tile transposed -> sVT[d][key]
        {
            const int key = tid >> 2;
            const int db  = (tid & 3) * 16;
            const float* src = vg + (size_t)(kt * BKV + key) * rs + db;
            const int kc = key >> 2;            // chunk within VT row
            const int kb = (key & 3) * 4;       // byte within chunk
#pragma unroll
            for (int q = 0; q < 4; q++) {
                float4 v = *(const float4*)(src + q * 4);
                const int d0 = db + q * 4;
                *(float*)(sVT + sw256(d0 + 0, kc) + kb) = f2tf32(v.x);
                *(float*)(sVT + sw256(d0 + 1, kc) + kb) = f2tf32(v.y);
                *(float*)(sVT + sw256(d0 + 2, kc) + kb) = f2tf32(v.z);
                *(float*)(sVT + sw256(d0 + 3, kc) + kb) = f2tf32(v.w);
            }
        }
        if (tid < BKV) sM[tid] = mg[kt * BKV + tid];
        __syncthreads();

        // ---- S = Q K^T : per warp 16 x 64
        float sacc[8][4];
#pragma unroll
        for (int j = 0; j < 8; j++)
#pragma unroll
            for (int r = 0; r < 4; r++) sacc[j][r] = 0.f;
#pragma unroll
        for (int ks = 0; ks < 8; ks++) {
            uint32_t bfr[8][2];
#pragma unroll
            for (int nf = 0; nf < 8; nf++)
                ldsm_x2(bfr[nf], aK + sw256(nf * 8 + bln, ks * 2 + bch));
#pragma unroll
            for (int nf = 0; nf < 8; nf++)
                mma_tf32(sacc[nf], qf[ks], bfr[nf]);
        }

        // ---- fragment softmax (rows: wid*16 + lane>>2, +8)
        float rmax0 = -1e30f, rmax1 = -1e30f;
#pragma unroll
        for (int j = 0; j < 8; j++) {
            const int c = j * 8 + (lane & 3) * 2;
            const int mk0 = sM[c], mk1 = sM[c + 1];
            sacc[j][0] = mk0 ? sacc[j][0] * 0.125f : -1e30f;
            sacc[j][1] = mk1 ? sacc[j][1] * 0.125f : -1e30f;
            sacc[j][2] = mk0 ? sacc[j][2] * 0.125f : -1e30f;
            sacc[j][3] = mk1 ? sacc[j][3] * 0.125f : -1e30f;
            rmax0 = fmaxf(rmax0, fmaxf(sacc[j][0], sacc[j][1]));
            rmax1 = fmaxf(rmax1, fmaxf(sacc[j][2], sacc[j][3]));
        }
        rmax0 = fmaxf(rmax0, __shfl_xor_sync(0xffffffffu, rmax0, 1));
        rmax0 = fmaxf(rmax0, __shfl_xor_sync(0xffffffffu, rmax0, 2));
        rmax1 = fmaxf(rmax1, __shfl_xor_sync(0xffffffffu, rmax1, 1));
        rmax1 = fmaxf(rmax1, __shfl_xor_sync(0xffffffffu, rmax1, 2));

        const float mn0 = fmaxf(m_i[0], rmax0);
        const float mn1 = fmaxf(m_i[1], rmax1);
        const float cr0 = __expf(m_i[0] - mn0);
        const float cr1 = __expf(m_i[1] - mn1);
        m_i[0] = mn0; m_i[1] = mn1;

        float rsum0 = 0.f, rsum1 = 0.f;
#pragma unroll
        for (int j = 0; j < 8; j++) {
            sacc[j][0] = __expf(sacc[j][0] - mn0);
            sacc[j][1] = __expf(sacc[j][1] - mn0);
            sacc[j][2] = __expf(sacc[j][2] - mn1);
            sacc[j][3] = __expf(sacc[j][3] - mn1);
            rsum0 += sacc[j][0] + sacc[j][1];
            rsum1 += sacc[j][2] + sacc[j][3];
        }
        rsum0 += __shfl_xor_sync(0xffffffffu, rsum0, 1);
        rsum0 += __shfl_xor_sync(0xffffffffu, rsum0, 2);
        rsum1 += __shfl_xor_sync(0xffffffffu, rsum1, 1);
        rsum1 += __shfl_xor_sync(0xffffffffu, rsum1, 2);
        l_i[0] = l_i[0] * cr0 + rsum0;
        l_i[1] = l_i[1] * cr1 + rsum1;

#pragma unroll
        for (int j = 0; j < 8; j++) {
            oacc[j][0] *= cr0; oacc[j][1] *= cr0;
            oacc[j][2] *= cr1; oacc[j][3] *= cr1;
        }

        // ---- store P (tf32) for PV mma; rows are warp-local
        {
            const int r0 = wid * 16 + (lane >> 2);
#pragma unroll
            for (int j = 0; j < 8; j++) {
                const int c = j * 8 + (lane & 3) * 2;
                const int ch = c >> 2;
                const int cb = (c & 3) * 4;
                float2 v0, v1;
                v0.x = f2tf32(sacc[j][0]); v0.y = f2tf32(sacc[j][1]);
                v1.x = f2tf32(sacc[j][2]); v1.y = f2tf32(sacc[j][3]);
                *(float2*)(sP + sw256(r0,     ch) + cb) = v0;
                *(float2*)(sP + sw256(r0 + 8, ch) + cb) = v1;
            }
        }
        __syncwarp();

        // ---- O += P V^T : A = P (k = keys), B = sVT (n = d, k = keys)
#pragma unroll
        for (int ks = 0; ks < 8; ks++) {
            uint32_t af[4];
            ldsm_x4(af, aP + sw256(arow, ks * 2 + ach));
            uint32_t bfr[8][2];
#pragma unroll
            for (int nf = 0; nf < 8; nf++)
                ldsm_x2(bfr[nf], aVT + sw256(nf * 8 + bln, ks * 2 + bch));
#pragma unroll
            for (int nf = 0; nf < 8; nf++)
                mma_tf32(oacc[nf], af, bfr[nf]);
        }
    }

    // ---- epilogue: normalize, write to [b, s, h*64 + d]
    const float inv0 = 1.0f / l_i[0];
    const float inv1 = 1.0f / l_i[1];
    const int r0 = qb * BQ + wid * 16 + (lane >> 2);
    const int c0 = h * HDIM + (lane & 3) * 2;
#pragma unroll
    for (int j = 0; j < 8; j++) {
        const int c = c0 + j * 8;
        float2 v0, v1;
        v0.x = oacc[j][0] * inv0; v0.y = oacc[j][1] * inv0;
        v1.x = oacc[j][2] * inv1; v1.y = oacc[j][3] * inv1;
        *(float2*)&out[(size_t)(b * SEQ + r0)     * EMBED + c] = v0;
        *(float2*)&out[(size_t)(b * SEQ + r0 + 8) * EMBED + c] = v1;
    }
}

// ---------------------------------------------------------------------------
extern "C" void kernel_launch(void* const* d_in, const int* in_sizes, int n_in,
                              void* d_out, int out_size)
{
    const float* x    = (const float*)d_in[0];
    const int*   mask = (const int*)  d_in[1];
    const float* Wqkv = (const float*)d_in[2];
    const float* bqkv = (const float*)d_in[3];
    const float* Wout = (const float*)d_in[4];
    const float* bout = (const float*)d_in[5];
    float* out = (float*)d_out;

    float *qkv = nullptr, *attn = nullptr;
    cudaGetSymbolAddress((void**)&qkv,  g_qkv);
    cudaGetSymbolAddress((void**)&attn, g_attn);

    cudaFuncSetAttribute(flash_attn_tc,
                         cudaFuncAttributeMaxDynamicSharedMemorySize, FA_SMEM);

    // 1) qkv = x @ Wqkv^T + bqkv       [4096, 3072]  (tf32 mma.sync)
    {
        dim3 grid((3 * EMBED) / 128, MTOT / 128);
        gemm_tf32_mma<<<grid, 256>>>(x, Wqkv, bqkv, qkv, MTOT, 3 * EMBED, EMBED);
    }
    // 2) flash attention -> attn       [4096, 1024]  (tf32 mma.sync)
    {
        dim3 grid(SEQ / BQ, HEADS, BATCH);
        flash_attn_tc<<<grid, 256, FA_SMEM>>>(qkv, mask, attn);
    }
    // 3) out = attn @ Wout^T + bout    [4096, 1024]  (tf32 mma.sync)
    {
        dim3 grid(EMBED / 128, MTOT / 128);
        gemm_tf32_mma<<<grid, 256>>>(attn, Wout, bout, out, MTOT, EMBED, EMBED);
    }
}